// round 14
// baseline (speedup 1.0000x reference)
#include <cuda_runtime.h>
#include <cuda_bf16.h>

#define H 4
#define Dh 64
#define HID 256
#define NGT 100000
#define NUBS 20000
#define NAG 20000
#define ESEEN 320000
#define ENEAR 160000

typedef unsigned long long u64;
typedef unsigned int u32;

__device__ __forceinline__ u64 pk2(float lo, float hi) {
    u64 r; asm("mov.b64 %0,{%1,%2};" : "=l"(r) : "f"(lo), "f"(hi)); return r;
}
__device__ __forceinline__ u64 f2fma(u64 a, u64 b, u64 c) {
    u64 d; asm("fma.rn.f32x2 %0,%1,%2,%3;" : "=l"(d) : "l"(a), "l"(b), "l"(c)); return d;
}
__device__ __forceinline__ float2 upk2(u64 v) {
    float2 r; asm("mov.b64 {%0,%1},%2;" : "=f"(r.x), "=f"(r.y) : "l"(v)); return r;
}

__device__ __forceinline__ void bfsplit(float v, unsigned short& h, unsigned short& l) {
    __nv_bfloat16 hb = __float2bfloat16_rn(v);
    h = __bfloat16_as_ushort(hb);
    float r = v - __bfloat162float(hb);
    l = __bfloat16_as_ushort(__float2bfloat16_rn(r));
}

__device__ __forceinline__ void mma_bf16(float* d, const u32* a, u32 b0, u32 b1) {
    asm volatile(
        "mma.sync.aligned.m16n8k16.row.col.f32.bf16.bf16.f32 "
        "{%0,%1,%2,%3},{%4,%5,%6,%7},{%8,%9},{%0,%1,%2,%3};"
        : "+f"(d[0]), "+f"(d[1]), "+f"(d[2]), "+f"(d[3])
        : "r"(a[0]), "r"(a[1]), "r"(a[2]), "r"(a[3]), "r"(b0), "r"(b1));
}

// ---------------- scratch (device globals, no runtime alloc) ----------------
// g_feat holds ONLY the 4 agent-side projections now (fs is recomputed in gat)
__device__ float g_feat[4 * NAG * HID];
__device__ u32   g_xh[NAG * 256];
__device__ u32   g_xl[NAG * 256];
__device__ uint2 g_wfh[32 * 256 * 4];
__device__ uint2 g_wfl[32 * 256 * 4];
__device__ int   g_cnt[2 * NAG];
__device__ int   g_cur[2 * NAG];
__device__ int   g_off[2 * NAG];
__device__ int   g_base[2];
__device__ int   g_perm[ESEEN + ENEAR];

#define FD_S    0L
#define RES_S   ((long)NAG * HID)
#define FD_N    ((long)2 * NAG * HID)
#define RES_N   ((long)3 * NAG * HID)

__global__ void k_zero() {
    int i = blockIdx.x * blockDim.x + threadIdx.x;
    if (i < 2 * NAG) g_cnt[i] = 0;
    if (i < 2) g_base[i] = 0;
}

// ---------------- W_aggr -> bf16 hi/lo in B-fragment layout ----------------
__global__ void k_wprep(const float* __restrict__ W) {
    int t = blockIdx.x * 256 + threadIdx.x;
    if (t >= 32 * 256 * 4) return;
    int ks = t >> 10, rem = t & 1023;
    int n = rem >> 2, tg = rem & 3;
    int k0 = ks * 16 + tg * 2;
    float v0 = W[(k0 + 0) * HID + n], v1 = W[(k0 + 1) * HID + n];
    float v2 = W[(k0 + 8) * HID + n], v3 = W[(k0 + 9) * HID + n];
    unsigned short h0, l0, h1, l1, h2, l2, h3, l3;
    bfsplit(v0, h0, l0); bfsplit(v1, h1, l1);
    bfsplit(v2, h2, l2); bfsplit(v3, h3, l3);
    g_wfh[t] = make_uint2((u32)h0 | ((u32)h1 << 16), (u32)h2 | ((u32)h3 << 16));
    g_wfl[t] = make_uint2((u32)l0 | ((u32)l1 << 16), (u32)l2 | ((u32)l3 << 16));
}

// ---------------- agent projections (F=16) ----------------
__device__ __forceinline__ void proj_body16(const float* __restrict__ x,
                                            const float* __restrict__ W,
                                            const float* __restrict__ b,
                                            int n, long out_off) {
    const int F = 16;
    int node0 = blockIdx.x * 128;
    if (node0 >= n) return;
    __shared__ float sx[128 * 16];
    int cnt = n - node0; if (cnt > 128) cnt = 128;
    int nf4 = (cnt * F) >> 2;
    for (int i = threadIdx.x; i < nf4; i += 256)
        *(float4*)(sx + i * 4) = *(const float4*)(x + (long)node0 * F + i * 4);
    __syncthreads();

    int warp = threadIdx.x >> 5, lane = threadIdx.x & 31;
    int c = (warp & 3) * 64 + (lane << 1);
    int nh = (warp >> 2) * 64;
    u64 wp[F];
#pragma unroll
    for (int k = 0; k < F; k++) wp[k] = *(const u64*)(W + k * HID + c);
    u64 bp = *(const u64*)(b + c);

    int jend = nh + 64; if (jend > cnt) jend = cnt;
#pragma unroll 1
    for (int j = nh; j < jend; j++) {
        const float* xr = sx + j * F;
        u64 acc = bp;
#pragma unroll
        for (int k4 = 0; k4 < F; k4 += 4) {
            float4 xv = *(const float4*)(xr + k4);
            acc = f2fma(pk2(xv.x, xv.x), wp[k4 + 0], acc);
            acc = f2fma(pk2(xv.y, xv.y), wp[k4 + 1], acc);
            acc = f2fma(pk2(xv.z, xv.z), wp[k4 + 2], acc);
            acc = f2fma(pk2(xv.w, xv.w), wp[k4 + 3], acc);
        }
        *(u64*)(g_feat + out_off + (long)(node0 + j) * HID + c) = acc;
    }
}

__global__ void k_proj_all(const float* xa,
                           const float* W0, const float* b0,
                           const float* W1, const float* b1,
                           const float* W2, const float* b2,
                           const float* W3, const float* b3, int n_ag) {
    switch (blockIdx.y) {
        case 0: proj_body16(xa, W0, b0, n_ag, FD_S);  break;
        case 1: proj_body16(xa, W1, b1, n_ag, RES_S); break;
        case 2: proj_body16(xa, W2, b2, n_ag, FD_N);  break;
        default: proj_body16(xa, W3, b3, n_ag, RES_N); break;
    }
}

// ---------------- CSR build ----------------
__global__ void k_hist(const int* __restrict__ dA, int eA,
                       const int* __restrict__ dB, int eB) {
    int g = blockIdx.y;
    const int* dst = g ? dB : dA;
    int e = g ? eB : eA;
    int co = g ? NAG : 0;
    for (int i = blockIdx.x * blockDim.x + threadIdx.x; i < e;
         i += gridDim.x * blockDim.x)
        atomicAdd(&g_cnt[co + __ldg(dst + i)], 1);
}

__global__ void k_assign(int n) {
    int i = blockIdx.x * blockDim.x + threadIdx.x;
    if (i >= 2 * n) return;
    int g = (i >= n) ? 1 : 0;
    int lane = threadIdx.x & 31;
    int c = g_cnt[i];
    int pre = c;
#pragma unroll
    for (int o = 1; o < 32; o <<= 1) {
        int v = __shfl_up_sync(0xffffffffu, pre, o);
        if (lane >= o) pre += v;
    }
    int total = __shfl_sync(0xffffffffu, pre, 31);
    int excl = pre - c;
    int base = 0;
    if (lane == 31) base = atomicAdd(&g_base[g], total);
    base = __shfl_sync(0xffffffffu, base, 31);
    g_off[i] = base + excl;
    g_cur[i] = base + excl;
}

__global__ void k_scatter(const int* __restrict__ dA, const int* __restrict__ sA, int eA,
                          const int* __restrict__ dB, const int* __restrict__ sB, int eB) {
    int g = blockIdx.y;
    const int* dst = g ? dB : dA;
    const int* src = g ? sB : sA;
    int e = g ? eB : eA;
    int pb = g ? ESEEN : 0;
    for (int i = blockIdx.x * blockDim.x + threadIdx.x; i < e;
         i += gridDim.x * blockDim.x) {
        int p = atomicAdd(&g_cur[g * NAG + __ldg(dst + i)], 1);
        g_perm[pb + p] = __ldg(src + i);
    }
}

// ---------------- GATv2 with on-the-fly fs recompute ----------------
// 2 warps per dst: warp half h owns cols [h*128, h*128+128) (2 heads).
// Lane owns 4 cols. fs[src] = x[src](8 floats, uniform 32B load) @ Ws + bs,
// computed in registers -> no 1KB gathers at all.
__device__ __forceinline__ float lrelu(float v) { return (v >= 0.f) ? v : 0.2f * v; }

__global__ void __launch_bounds__(256) k_gat(
    const float* __restrict__ attnS, const float* __restrict__ attnN,
    const float* __restrict__ xg, const float* __restrict__ xu,
    const float* __restrict__ WsS, const float* __restrict__ bsS,
    const float* __restrict__ WsN, const float* __restrict__ bsN, int nag) {
    int g = blockIdx.y;
    const float* attn = g ? attnN : attnS;
    const float* xsrc = g ? xu : xg;
    const float* Ws   = g ? WsN : WsS;
    const float* bs   = g ? bsN : bsS;
    long fd_off  = g ? FD_N  : FD_S;
    long res_off = g ? RES_N : RES_S;
    int gbase    = g ? NAG : 0;
    int pb       = g ? ESEEN : 0;

    int warp = threadIdx.x >> 5, lane = threadIdx.x & 31;
    int w = blockIdx.x * 8 + warp;
    int dstn = w >> 1;
    if (dstn >= nag) return;
    int half = w & 1;
    int col = half * 128 + lane * 4;

    // Ws column-slice (8 k-rows x 4 cols) + bias in registers
    u64 W0[8], W1[8];
#pragma unroll
    for (int k = 0; k < 8; k++) {
        ulonglong2 wv = *(const ulonglong2*)(Ws + k * HID + col);
        W0[k] = wv.x; W1[k] = wv.y;
    }
    ulonglong2 bv = *(const ulonglong2*)(bs + col);

    float4 a  = __ldg((const float4*)(attn + col));
    float4 fd = *(const float4*)(g_feat + fd_off + (long)dstn * HID + col);

    int e0 = g_off[gbase + dstn];
    int e1 = e0 + g_cnt[gbase + dstn];
    const int* pp = g_perm + pb;

    int id0 = 0, id1 = 0, id2 = 0, id3 = 0;
    if (e0 < e1) {
        int rr = e1 - e0;
        id0 = pp[e0];
        id1 = (rr > 1) ? pp[e0 + 1] : id0;
        id2 = (rr > 2) ? pp[e0 + 2] : id0;
        id3 = (rr > 3) ? pp[e0 + 3] : id0;
    }

    float mx = -3.0e38f, den = 0.f;
    float4 agg = make_float4(0.f, 0.f, 0.f, 0.f);

    for (int i = e0; i < e1; i += 4) {
        // uniform 32B x-row loads (L2-resident), 8 in flight
        const float* x0 = xsrc + (long)id0 * 8;
        const float* x1 = xsrc + (long)id1 * 8;
        const float* x2 = xsrc + (long)id2 * 8;
        const float* x3 = xsrc + (long)id3 * 8;
        float4 xa0 = __ldg((const float4*)x0), xb0 = __ldg((const float4*)(x0 + 4));
        float4 xa1 = __ldg((const float4*)x1), xb1 = __ldg((const float4*)(x1 + 4));
        float4 xa2 = __ldg((const float4*)x2), xb2 = __ldg((const float4*)(x2 + 4));
        float4 xa3 = __ldg((const float4*)x3), xb3 = __ldg((const float4*)(x3 + 4));

        // prefetch next chunk's ids
        if (i + 4 < e1) {
            int j = i + 4, rr = e1 - j;
            id0 = pp[j];
            id1 = (rr > 1) ? pp[j + 1] : id0;
            id2 = (rr > 2) ? pp[j + 2] : id0;
            id3 = (rr > 3) ? pp[j + 3] : id0;
        }

        // recompute fs (4 cols) per edge: 16 f2fma each
        float4 fsv[4]; float p[4];
#pragma unroll
        for (int k = 0; k < 4; k++) {
            float4 xa = (k == 0) ? xa0 : (k == 1) ? xa1 : (k == 2) ? xa2 : xa3;
            float4 xb = (k == 0) ? xb0 : (k == 1) ? xb1 : (k == 2) ? xb2 : xb3;
            u64 c0 = bv.x, c1 = bv.y;
            u64 xp;
            xp = pk2(xa.x, xa.x); c0 = f2fma(xp, W0[0], c0); c1 = f2fma(xp, W1[0], c1);
            xp = pk2(xa.y, xa.y); c0 = f2fma(xp, W0[1], c0); c1 = f2fma(xp, W1[1], c1);
            xp = pk2(xa.z, xa.z); c0 = f2fma(xp, W0[2], c0); c1 = f2fma(xp, W1[2], c1);
            xp = pk2(xa.w, xa.w); c0 = f2fma(xp, W0[3], c0); c1 = f2fma(xp, W1[3], c1);
            xp = pk2(xb.x, xb.x); c0 = f2fma(xp, W0[4], c0); c1 = f2fma(xp, W1[4], c1);
            xp = pk2(xb.y, xb.y); c0 = f2fma(xp, W0[5], c0); c1 = f2fma(xp, W1[5], c1);
            xp = pk2(xb.z, xb.z); c0 = f2fma(xp, W0[6], c0); c1 = f2fma(xp, W1[6], c1);
            xp = pk2(xb.w, xb.w); c0 = f2fma(xp, W0[7], c0); c1 = f2fma(xp, W1[7], c1);
            float2 lo = upk2(c0), hi = upk2(c1);
            fsv[k] = make_float4(lo.x, lo.y, hi.x, hi.y);
            float pv;
            pv = lrelu(fsv[k].x + fd.x) * a.x;
            pv = fmaf(lrelu(fsv[k].y + fd.y), a.y, pv);
            pv = fmaf(lrelu(fsv[k].z + fd.z), a.z, pv);
            pv = fmaf(lrelu(fsv[k].w + fd.w), a.w, pv);
            p[k] = pv;
        }
        // segmented sum over the 16 lanes of each head
#pragma unroll
        for (int o = 1; o < 16; o <<= 1) {
            p[0] += __shfl_xor_sync(0xffffffffu, p[0], o);
            p[1] += __shfl_xor_sync(0xffffffffu, p[1], o);
            p[2] += __shfl_xor_sync(0xffffffffu, p[2], o);
            p[3] += __shfl_xor_sync(0xffffffffu, p[3], o);
        }
        int r = e1 - i;
        if (r < 2) p[1] = -3.0e38f;
        if (r < 3) p[2] = -3.0e38f;
        if (r < 4) p[3] = -3.0e38f;

        float cm = fmaxf(fmaxf(p[0], p[1]), fmaxf(p[2], p[3]));
        float nmx = fmaxf(mx, cm);
        float scale = __expf(mx - nmx);
        float ex0 = __expf(p[0] - nmx);
        float ex1 = __expf(p[1] - nmx);
        float ex2 = __expf(p[2] - nmx);
        float ex3 = __expf(p[3] - nmx);
        den = fmaf(den, scale, (ex0 + ex1) + (ex2 + ex3));
        agg.x = fmaf(agg.x, scale, fmaf(ex0, fsv[0].x, fmaf(ex1, fsv[1].x, fmaf(ex2, fsv[2].x, ex3 * fsv[3].x))));
        agg.y = fmaf(agg.y, scale, fmaf(ex0, fsv[0].y, fmaf(ex1, fsv[1].y, fmaf(ex2, fsv[2].y, ex3 * fsv[3].y))));
        agg.z = fmaf(agg.z, scale, fmaf(ex0, fsv[0].z, fmaf(ex1, fsv[1].z, fmaf(ex2, fsv[2].z, ex3 * fsv[3].z))));
        agg.w = fmaf(agg.w, scale, fmaf(ex0, fsv[0].w, fmaf(ex1, fsv[1].w, fmaf(ex2, fsv[2].w, ex3 * fsv[3].w))));
        mx = nmx;
    }

    float4 rv = *(const float4*)(g_feat + res_off + (long)dstn * HID + col);
    float inv = (e1 == e0) ? 1.f : (1.f / den);
    float o0 = fmaxf(fmaf(agg.x, inv, rv.x), 0.f);
    float o1 = fmaxf(fmaf(agg.y, inv, rv.y), 0.f);
    float o2 = fmaxf(fmaf(agg.z, inv, rv.z), 0.f);
    float o3 = fmaxf(fmaf(agg.w, inv, rv.w), 0.f);

    unsigned short h0, l0, h1, l1, h2, l2, h3, l3;
    bfsplit(o0, h0, l0); bfsplit(o1, h1, l1);
    bfsplit(o2, h2, l2); bfsplit(o3, h3, l3);
    int pidx = dstn * 256 + g * 128 + half * 64 + lane * 2;
    *(uint2*)(g_xh + pidx) = make_uint2((u32)h0 | ((u32)h1 << 16),
                                        (u32)h2 | ((u32)h3 << 16));
    *(uint2*)(g_xl + pidx) = make_uint2((u32)l0 | ((u32)l1 << 16),
                                        (u32)l2 | ((u32)l3 << 16));
}

// ---------------- final GEMM via split-bf16 mma.sync ----------------
__global__ void __launch_bounds__(256) k_gemm(const float* __restrict__ bias,
                                              float* __restrict__ C, int M) {
    const int N = HID;
    int warp = threadIdx.x >> 5, lane = threadIdx.x & 31;
    int g = lane >> 2, tg = lane & 3;
    int bm = blockIdx.y * 128, bn = blockIdx.x * 128;
    int wm = (warp >> 1) * 32, wn = (warp & 1) * 64;

    float acc[2][8][4];
#pragma unroll
    for (int mt = 0; mt < 2; mt++)
#pragma unroll
        for (int nt = 0; nt < 8; nt++)
#pragma unroll
            for (int q = 0; q < 4; q++) acc[mt][nt][q] = 0.f;

#pragma unroll 1
    for (int ks = 0; ks < 32; ks++) {
        u32 ah[2][4], al[2][4];
        int pb = ks * 8 + tg;
#pragma unroll
        for (int mt = 0; mt < 2; mt++) {
            int r0 = bm + wm + mt * 16 + g;
            int r1 = r0 + 8;
            if (r0 > M - 1) r0 = M - 1;
            if (r1 > M - 1) r1 = M - 1;
            ah[mt][0] = g_xh[r0 * 256 + pb];
            ah[mt][1] = g_xh[r1 * 256 + pb];
            ah[mt][2] = g_xh[r0 * 256 + pb + 4];
            ah[mt][3] = g_xh[r1 * 256 + pb + 4];
            al[mt][0] = g_xl[r0 * 256 + pb];
            al[mt][1] = g_xl[r1 * 256 + pb];
            al[mt][2] = g_xl[r0 * 256 + pb + 4];
            al[mt][3] = g_xl[r1 * 256 + pb + 4];
        }
        const uint2* wh = g_wfh + (ks * 256 + bn + wn) * 4 + lane;
        const uint2* wl = g_wfl + (ks * 256 + bn + wn) * 4 + lane;
#pragma unroll
        for (int nt = 0; nt < 8; nt++) {
            uint2 bh = __ldg(wh + nt * 32);
            uint2 bl = __ldg(wl + nt * 32);
#pragma unroll
            for (int mt = 0; mt < 2; mt++) {
                mma_bf16(acc[mt][nt], ah[mt], bh.x, bh.y);
                mma_bf16(acc[mt][nt], ah[mt], bl.x, bl.y);
                mma_bf16(acc[mt][nt], al[mt], bh.x, bh.y);
            }
        }
    }

#pragma unroll
    for (int mt = 0; mt < 2; mt++) {
        int r0 = bm + wm + mt * 16 + g;
        int r1 = r0 + 8;
#pragma unroll
        for (int nt = 0; nt < 8; nt++) {
            int n0 = bn + wn + nt * 8 + tg * 2;
            float b0f = bias[n0], b1f = bias[n0 + 1];
            if (r0 < M) {
                float2 v;
                v.x = fmaxf(acc[mt][nt][0] + b0f, 0.f);
                v.y = fmaxf(acc[mt][nt][1] + b1f, 0.f);
                *(float2*)(C + (long)r0 * N + n0) = v;
            }
            if (r1 < M) {
                float2 v;
                v.x = fmaxf(acc[mt][nt][2] + b0f, 0.f);
                v.y = fmaxf(acc[mt][nt][3] + b1f, 0.f);
                *(float2*)(C + (long)r1 * N + n0) = v;
            }
        }
    }
}

// ---------------- launch ----------------
extern "C" void kernel_launch(void* const* d_in, const int* in_sizes, int n_in,
                              void* d_out, int out_size) {
    const float* x_gt   = (const float*)d_in[0];
    const float* x_ubs  = (const float*)d_in[1];
    const float* x_ag   = (const float*)d_in[2];
    const int* seen_src = (const int*)d_in[3];
    const int* seen_dst = (const int*)d_in[4];
    const int* near_src = (const int*)d_in[5];
    const int* near_dst = (const int*)d_in[6];
    const float* Ws_seen = (const float*)d_in[7];
    const float* bs_seen = (const float*)d_in[8];
    const float* Wd_seen = (const float*)d_in[9];
    const float* bd_seen = (const float*)d_in[10];
    const float* attn_seen = (const float*)d_in[11];
    const float* Wr_seen = (const float*)d_in[12];
    const float* br_seen = (const float*)d_in[13];
    const float* Ws_near = (const float*)d_in[14];
    const float* bs_near = (const float*)d_in[15];
    const float* Wd_near = (const float*)d_in[16];
    const float* bd_near = (const float*)d_in[17];
    const float* attn_near = (const float*)d_in[18];
    const float* Wr_near = (const float*)d_in[19];
    const float* br_near = (const float*)d_in[20];
    const float* W_aggr  = (const float*)d_in[21];
    const float* b_aggr  = (const float*)d_in[22];
    float* out = (float*)d_out;

    int n_ag  = in_sizes[2] / 16;
    int e_seen = in_sizes[3];
    int e_near = in_sizes[5];

    static cudaStream_t s2 = nullptr;
    static cudaEvent_t evFork = nullptr, evJoin = nullptr;
    if (!s2) {
        cudaStreamCreateWithFlags(&s2, cudaStreamNonBlocking);
        cudaEventCreateWithFlags(&evFork, cudaEventDisableTiming);
        cudaEventCreateWithFlags(&evJoin, cudaEventDisableTiming);
    }

    // fork: CSR chain + W prep on s2 (independent of agent projections)
    cudaEventRecord(evFork, 0);
    cudaStreamWaitEvent(s2, evFork, 0);

    k_wprep<<<128, 256, 0, s2>>>(W_aggr);
    k_zero<<<(2 * NAG + 255) / 256, 256, 0, s2>>>();
    k_hist<<<dim3(256, 2), 256, 0, s2>>>(seen_dst, e_seen, near_dst, e_near);
    k_assign<<<(2 * n_ag + 255) / 256, 256, 0, s2>>>(n_ag);
    k_scatter<<<dim3(256, 2), 256, 0, s2>>>(seen_dst, seen_src, e_seen,
                                            near_dst, near_src, e_near);
    cudaEventRecord(evJoin, s2);

    // agent projections on the main stream (fs never materialized)
    k_proj_all<<<dim3((n_ag + 127) / 128, 4), 256>>>(x_ag,
        Wd_seen, bd_seen, Wr_seen, br_seen,
        Wd_near, bd_near, Wr_near, br_near, n_ag);

    cudaStreamWaitEvent(0, evJoin, 0);

    // 2 warps per dst, 8 warps per block
    k_gat<<<dim3((2 * n_ag + 7) / 8, 2), 256>>>(
        attn_seen, attn_near, x_gt, x_ubs,
        Ws_seen, bs_seen, Ws_near, bs_near, n_ag);

    k_gemm<<<dim3(HID / 128, (n_ag + 127) / 128), 256>>>(b_aggr, out, n_ag);
}

// round 15
// speedup vs baseline: 1.1797x; 1.1797x over previous
#include <cuda_runtime.h>
#include <cuda_bf16.h>

#define H 4
#define Dh 64
#define HID 256
#define NGT 100000
#define NUBS 20000
#define NAG 20000
#define ESEEN 320000
#define ENEAR 160000

typedef unsigned long long u64;
typedef unsigned int u32;

__device__ __forceinline__ u64 pk2(float lo, float hi) {
    u64 r; asm("mov.b64 %0,{%1,%2};" : "=l"(r) : "f"(lo), "f"(hi)); return r;
}
__device__ __forceinline__ u64 f2fma(u64 a, u64 b, u64 c) {
    u64 d; asm("fma.rn.f32x2 %0,%1,%2,%3;" : "=l"(d) : "l"(a), "l"(b), "l"(c)); return d;
}
__device__ __forceinline__ void pref_l2(const void* p) {
    asm volatile("prefetch.global.L2 [%0];" :: "l"(p));
}

__device__ __forceinline__ void bfsplit(float v, unsigned short& h, unsigned short& l) {
    __nv_bfloat16 hb = __float2bfloat16_rn(v);
    h = __bfloat16_as_ushort(hb);
    float r = v - __bfloat162float(hb);
    l = __bfloat16_as_ushort(__float2bfloat16_rn(r));
}

__device__ __forceinline__ void mma_bf16(float* d, const u32* a, u32 b0, u32 b1) {
    asm volatile(
        "mma.sync.aligned.m16n8k16.row.col.f32.bf16.bf16.f32 "
        "{%0,%1,%2,%3},{%4,%5,%6,%7},{%8,%9},{%0,%1,%2,%3};"
        : "+f"(d[0]), "+f"(d[1]), "+f"(d[2]), "+f"(d[3])
        : "r"(a[0]), "r"(a[1]), "r"(a[2]), "r"(a[3]), "r"(b0), "r"(b1));
}

// ---------------- scratch (device globals, no runtime alloc) ----------------
__device__ float g_feat[(NGT + NUBS + 4 * NAG) * HID];
__device__ u32   g_xh[NAG * 256];         // xcat hi: bf16x2 pairs
__device__ u32   g_xl[NAG * 256];         // xcat lo
__device__ uint2 g_wfh[32 * 256 * 4];     // W_aggr hi, mma-B-fragment layout
__device__ uint2 g_wfl[32 * 256 * 4];     // W_aggr lo
__device__ int   g_cnt[2 * NAG];
__device__ int   g_cur[2 * NAG];
__device__ int   g_off[2 * NAG];
__device__ int   g_base[2];
__device__ int   g_perm[ESEEN + ENEAR];

#define FS_SEEN 0L
#define FS_NEAR ((long)NGT * HID)
#define FD_S    ((long)(NGT + NUBS) * HID)
#define RES_S   (FD_S + (long)NAG * HID)
#define FD_N    (RES_S + (long)NAG * HID)
#define RES_N   (FD_N + (long)NAG * HID)

__global__ void k_zero() {
    int i = blockIdx.x * blockDim.x + threadIdx.x;
    if (i < 2 * NAG) g_cnt[i] = 0;
    if (i < 2) g_base[i] = 0;
}

// ---------------- W_aggr -> bf16 hi/lo in B-fragment layout ----------------
__global__ void k_wprep(const float* __restrict__ W) {
    int t = blockIdx.x * 256 + threadIdx.x;
    if (t >= 32 * 256 * 4) return;
    int ks = t >> 10, rem = t & 1023;
    int n = rem >> 2, tg = rem & 3;
    int k0 = ks * 16 + tg * 2;
    float v0 = W[(k0 + 0) * HID + n], v1 = W[(k0 + 1) * HID + n];
    float v2 = W[(k0 + 8) * HID + n], v3 = W[(k0 + 9) * HID + n];
    unsigned short h0, l0, h1, l1, h2, l2, h3, l3;
    bfsplit(v0, h0, l0); bfsplit(v1, h1, l1);
    bfsplit(v2, h2, l2); bfsplit(v3, h3, l3);
    g_wfh[t] = make_uint2((u32)h0 | ((u32)h1 << 16), (u32)h2 | ((u32)h3 << 16));
    g_wfl[t] = make_uint2((u32)l0 | ((u32)l1 << 16), (u32)l2 | ((u32)l3 << 16));
}

// ---------------- fused projections ----------------
template<int F>
__device__ __forceinline__ void proj_body(const float* __restrict__ x,
                                          const float* __restrict__ W,
                                          const float* __restrict__ b,
                                          int n, long out_off) {
    int node0 = blockIdx.x * 128;
    if (node0 >= n) return;
    __shared__ float sx[128 * 16];
    int cnt = n - node0; if (cnt > 128) cnt = 128;
    int nf4 = (cnt * F) >> 2;
    for (int i = threadIdx.x; i < nf4; i += 256)
        *(float4*)(sx + i * 4) = *(const float4*)(x + (long)node0 * F + i * 4);
    __syncthreads();

    int warp = threadIdx.x >> 5, lane = threadIdx.x & 31;
    int c = (warp & 3) * 64 + (lane << 1);
    int nh = (warp >> 2) * 64;
    u64 wp[F];
#pragma unroll
    for (int k = 0; k < F; k++) wp[k] = *(const u64*)(W + k * HID + c);
    u64 bp = *(const u64*)(b + c);

    int jend = nh + 64; if (jend > cnt) jend = cnt;
#pragma unroll 1
    for (int j = nh; j < jend; j++) {
        const float* xr = sx + j * F;
        u64 acc = bp;
#pragma unroll
        for (int k4 = 0; k4 < F; k4 += 4) {
            float4 xv = *(const float4*)(xr + k4);
            acc = f2fma(pk2(xv.x, xv.x), wp[k4 + 0], acc);
            acc = f2fma(pk2(xv.y, xv.y), wp[k4 + 1], acc);
            acc = f2fma(pk2(xv.z, xv.z), wp[k4 + 2], acc);
            acc = f2fma(pk2(xv.w, xv.w), wp[k4 + 3], acc);
        }
        *(u64*)(g_feat + out_off + (long)(node0 + j) * HID + c) = acc;
    }
}

__global__ void k_proj_all(const float* xg, const float* xu, const float* xa,
                           const float* Wsg, const float* bsg,
                           const float* Wsu, const float* bsu,
                           const float* W0, const float* b0,
                           const float* W1, const float* b1,
                           const float* W2, const float* b2,
                           const float* W3, const float* b3,
                           int n_gt, int n_ubs, int n_ag) {
    switch (blockIdx.y) {
        case 0: proj_body<8>(xg, Wsg, bsg, n_gt, FS_SEEN); break;
        case 1: proj_body<8>(xu, Wsu, bsu, n_ubs, FS_NEAR); break;
        case 2: proj_body<16>(xa, W0, b0, n_ag, FD_S);  break;
        case 3: proj_body<16>(xa, W1, b1, n_ag, RES_S); break;
        case 4: proj_body<16>(xa, W2, b2, n_ag, FD_N);  break;
        default: proj_body<16>(xa, W3, b3, n_ag, RES_N); break;
    }
}

// ---------------- CSR build ----------------
__global__ void k_hist(const int* __restrict__ dA, int eA,
                       const int* __restrict__ dB, int eB) {
    int g = blockIdx.y;
    const int* dst = g ? dB : dA;
    int e = g ? eB : eA;
    int co = g ? NAG : 0;
    for (int i = blockIdx.x * blockDim.x + threadIdx.x; i < e;
         i += gridDim.x * blockDim.x)
        atomicAdd(&g_cnt[co + __ldg(dst + i)], 1);
}

__global__ void k_assign(int n) {
    int i = blockIdx.x * blockDim.x + threadIdx.x;
    if (i >= 2 * n) return;
    int g = (i >= n) ? 1 : 0;
    int lane = threadIdx.x & 31;
    int c = g_cnt[i];
    int pre = c;
#pragma unroll
    for (int o = 1; o < 32; o <<= 1) {
        int v = __shfl_up_sync(0xffffffffu, pre, o);
        if (lane >= o) pre += v;
    }
    int total = __shfl_sync(0xffffffffu, pre, 31);
    int excl = pre - c;
    int base = 0;
    if (lane == 31) base = atomicAdd(&g_base[g], total);
    base = __shfl_sync(0xffffffffu, base, 31);
    g_off[i] = base + excl;
    g_cur[i] = base + excl;
}

__global__ void k_scatter(const int* __restrict__ dA, const int* __restrict__ sA, int eA,
                          const int* __restrict__ dB, const int* __restrict__ sB, int eB) {
    int g = blockIdx.y;
    const int* dst = g ? dB : dA;
    const int* src = g ? sB : sA;
    int e = g ? eB : eA;
    int pb = g ? ESEEN : 0;
    for (int i = blockIdx.x * blockDim.x + threadIdx.x; i < e;
         i += gridDim.x * blockDim.x) {
        int p = atomicAdd(&g_cur[g * NAG + __ldg(dst + i)], 1);
        g_perm[pb + p] = __ldg(src + i);
    }
}

// ---------------- GATv2: one warp per dst, chunk-of-4 + L2 row prefetch --------
__device__ __forceinline__ float lrelu(float v) { return (v >= 0.f) ? v : 0.2f * v; }

__device__ __forceinline__ float escore(float4 fa, float4 fb, float4 d0, float4 d1,
                                        float4 a0, float4 a1) {
    float p;
    p = lrelu(fa.x + d0.x) * a0.x;
    p = fmaf(lrelu(fa.y + d0.y), a0.y, p);
    p = fmaf(lrelu(fa.z + d0.z), a0.z, p);
    p = fmaf(lrelu(fa.w + d0.w), a0.w, p);
    p = fmaf(lrelu(fb.x + d1.x), a1.x, p);
    p = fmaf(lrelu(fb.y + d1.y), a1.y, p);
    p = fmaf(lrelu(fb.z + d1.z), a1.z, p);
    p = fmaf(lrelu(fb.w + d1.w), a1.w, p);
    return p;
}

__global__ void __launch_bounds__(256) k_gat(const float* __restrict__ attnS,
                                             const float* __restrict__ attnN, int nag) {
    int g = blockIdx.y;
    const float* attn = g ? attnN : attnS;
    long fs_off  = g ? FS_NEAR : FS_SEEN;
    long fd_off  = g ? FD_N    : FD_S;
    long res_off = g ? RES_N   : RES_S;
    int gbase    = g ? NAG : 0;
    int pb       = g ? ESEEN : 0;
    int xoff     = g ? HID : 0;

    int warp = threadIdx.x >> 5, lane = threadIdx.x & 31;
    int dstn = blockIdx.x * 8 + warp;
    if (dstn >= nag) return;
    int off = lane * 8;

    float4 a0 = __ldg((const float4*)(attn + off));
    float4 a1 = __ldg((const float4*)(attn + off + 4));
    const float* fdr = g_feat + fd_off + (long)dstn * HID + off;
    float4 d0 = *(const float4*)(fdr);
    float4 d1 = *(const float4*)(fdr + 4);
    const float* rvr = g_feat + res_off + (long)dstn * HID + off;
    float4 r0 = *(const float4*)(rvr);
    float4 r1 = *(const float4*)(rvr + 4);

    int e0 = g_off[gbase + dstn];
    int e1 = e0 + g_cnt[gbase + dstn];
    const float* fs = g_feat + fs_off;
    const int* pp = g_perm + pb;

    int ia[4], ib[4];                       // current / next chunk ids
    auto ldids = [&](int j, int* o) {
        int rr = e1 - j;
        o[0] = pp[j];
        o[1] = (rr > 1) ? pp[j + 1] : o[0];
        o[2] = (rr > 2) ? pp[j + 2] : o[0];
        o[3] = (rr > 3) ? pp[j + 3] : o[0];
    };
    auto prefetch4 = [&](const int* id) {
#pragma unroll
        for (int k = 0; k < 4; k++)
            pref_l2(fs + (long)id[k] * HID + off);
    };
    if (e0 < e1) {
        ldids(e0, ia);
        prefetch4(ia);
        if (e0 + 4 < e1) { ldids(e0 + 4, ib); prefetch4(ib); }
    }

    float mx = -3.0e38f, den = 0.f;
    float4 acc0 = make_float4(0.f, 0.f, 0.f, 0.f), acc1 = acc0;

    for (int i = e0; i < e1; i += 4) {
        const float* p0r = fs + (long)ia[0] * HID + off;
        const float* p1r = fs + (long)ia[1] * HID + off;
        const float* p2r = fs + (long)ia[2] * HID + off;
        const float* p3r = fs + (long)ia[3] * HID + off;
        float4 f0a = __ldg((const float4*)p0r), f0b = __ldg((const float4*)(p0r + 4));
        float4 f1a = __ldg((const float4*)p1r), f1b = __ldg((const float4*)(p1r + 4));
        float4 f2a = __ldg((const float4*)p2r), f2b = __ldg((const float4*)(p2r + 4));
        float4 f3a = __ldg((const float4*)p3r), f3b = __ldg((const float4*)(p3r + 4));

        // fetch ids 2 chunks ahead + prefetch their rows to L2 (~700cyc lead)
        int ic[4];
        bool hn2 = (i + 8 < e1);
        if (hn2) { ldids(i + 8, ic); prefetch4(ic); }

        float p0 = escore(f0a, f0b, d0, d1, a0, a1);
        float p1 = escore(f1a, f1b, d0, d1, a0, a1);
        float p2 = escore(f2a, f2b, d0, d1, a0, a1);
        float p3 = escore(f3a, f3b, d0, d1, a0, a1);
#pragma unroll
        for (int o = 1; o < 8; o <<= 1) {
            p0 += __shfl_xor_sync(0xffffffffu, p0, o);
            p1 += __shfl_xor_sync(0xffffffffu, p1, o);
            p2 += __shfl_xor_sync(0xffffffffu, p2, o);
            p3 += __shfl_xor_sync(0xffffffffu, p3, o);
        }
        int r = e1 - i;
        if (r < 2) p1 = -3.0e38f;
        if (r < 3) p2 = -3.0e38f;
        if (r < 4) p3 = -3.0e38f;

        float cm = fmaxf(fmaxf(p0, p1), fmaxf(p2, p3));
        float nmx = fmaxf(mx, cm);
        float scale = __expf(mx - nmx);
        float x0 = __expf(p0 - nmx);
        float x1 = __expf(p1 - nmx);
        float x2 = __expf(p2 - nmx);
        float x3 = __expf(p3 - nmx);
        den = fmaf(den, scale, (x0 + x1) + (x2 + x3));
        acc0.x = fmaf(acc0.x, scale, fmaf(x0, f0a.x, fmaf(x1, f1a.x, fmaf(x2, f2a.x, x3 * f3a.x))));
        acc0.y = fmaf(acc0.y, scale, fmaf(x0, f0a.y, fmaf(x1, f1a.y, fmaf(x2, f2a.y, x3 * f3a.y))));
        acc0.z = fmaf(acc0.z, scale, fmaf(x0, f0a.z, fmaf(x1, f1a.z, fmaf(x2, f2a.z, x3 * f3a.z))));
        acc0.w = fmaf(acc0.w, scale, fmaf(x0, f0a.w, fmaf(x1, f1a.w, fmaf(x2, f2a.w, x3 * f3a.w))));
        acc1.x = fmaf(acc1.x, scale, fmaf(x0, f0b.x, fmaf(x1, f1b.x, fmaf(x2, f2b.x, x3 * f3b.x))));
        acc1.y = fmaf(acc1.y, scale, fmaf(x0, f0b.y, fmaf(x1, f1b.y, fmaf(x2, f2b.y, x3 * f3b.y))));
        acc1.z = fmaf(acc1.z, scale, fmaf(x0, f0b.z, fmaf(x1, f1b.z, fmaf(x2, f2b.z, x3 * f3b.z))));
        acc1.w = fmaf(acc1.w, scale, fmaf(x0, f0b.w, fmaf(x1, f1b.w, fmaf(x2, f2b.w, x3 * f3b.w))));
        mx = nmx;
#pragma unroll
        for (int k = 0; k < 4; k++) { ia[k] = ib[k]; if (hn2) ib[k] = ic[k]; }
    }
    float inv = (e1 == e0) ? 1.f : (1.f / den);
    float o[8];
    o[0] = fmaxf(fmaf(acc0.x, inv, r0.x), 0.f);
    o[1] = fmaxf(fmaf(acc0.y, inv, r0.y), 0.f);
    o[2] = fmaxf(fmaf(acc0.z, inv, r0.z), 0.f);
    o[3] = fmaxf(fmaf(acc0.w, inv, r0.w), 0.f);
    o[4] = fmaxf(fmaf(acc1.x, inv, r1.x), 0.f);
    o[5] = fmaxf(fmaf(acc1.y, inv, r1.y), 0.f);
    o[6] = fmaxf(fmaf(acc1.z, inv, r1.z), 0.f);
    o[7] = fmaxf(fmaf(acc1.w, inv, r1.w), 0.f);
    u32 hp[4], lp[4];
#pragma unroll
    for (int j = 0; j < 4; j++) {
        unsigned short h0, l0, h1, l1;
        bfsplit(o[2 * j], h0, l0);
        bfsplit(o[2 * j + 1], h1, l1);
        hp[j] = (u32)h0 | ((u32)h1 << 16);
        lp[j] = (u32)l0 | ((u32)l1 << 16);
    }
    int pidx = dstn * 256 + (xoff >> 1) + lane * 4;
    *(uint4*)(g_xh + pidx) = make_uint4(hp[0], hp[1], hp[2], hp[3]);
    *(uint4*)(g_xl + pidx) = make_uint4(lp[0], lp[1], lp[2], lp[3]);
}

// ---------------- final GEMM via split-bf16 mma.sync ----------------
__global__ void __launch_bounds__(256) k_gemm(const float* __restrict__ bias,
                                              float* __restrict__ C, int M) {
    const int N = HID;
    int warp = threadIdx.x >> 5, lane = threadIdx.x & 31;
    int g = lane >> 2, tg = lane & 3;
    int bm = blockIdx.y * 128, bn = blockIdx.x * 128;
    int wm = (warp >> 1) * 32, wn = (warp & 1) * 64;

    float acc[2][8][4];
#pragma unroll
    for (int mt = 0; mt < 2; mt++)
#pragma unroll
        for (int nt = 0; nt < 8; nt++)
#pragma unroll
            for (int q = 0; q < 4; q++) acc[mt][nt][q] = 0.f;

#pragma unroll 1
    for (int ks = 0; ks < 32; ks++) {
        u32 ah[2][4], al[2][4];
        int pb = ks * 8 + tg;
#pragma unroll
        for (int mt = 0; mt < 2; mt++) {
            int r0 = bm + wm + mt * 16 + g;
            int r1 = r0 + 8;
            if (r0 > M - 1) r0 = M - 1;
            if (r1 > M - 1) r1 = M - 1;
            ah[mt][0] = g_xh[r0 * 256 + pb];
            ah[mt][1] = g_xh[r1 * 256 + pb];
            ah[mt][2] = g_xh[r0 * 256 + pb + 4];
            ah[mt][3] = g_xh[r1 * 256 + pb + 4];
            al[mt][0] = g_xl[r0 * 256 + pb];
            al[mt][1] = g_xl[r1 * 256 + pb];
            al[mt][2] = g_xl[r0 * 256 + pb + 4];
            al[mt][3] = g_xl[r1 * 256 + pb + 4];
        }
        const uint2* wh = g_wfh + (ks * 256 + bn + wn) * 4 + lane;
        const uint2* wl = g_wfl + (ks * 256 + bn + wn) * 4 + lane;
#pragma unroll
        for (int nt = 0; nt < 8; nt++) {
            uint2 bh = __ldg(wh + nt * 32);
            uint2 bl = __ldg(wl + nt * 32);
#pragma unroll
            for (int mt = 0; mt < 2; mt++) {
                mma_bf16(acc[mt][nt], ah[mt], bh.x, bh.y);
                mma_bf16(acc[mt][nt], ah[mt], bl.x, bl.y);
                mma_bf16(acc[mt][nt], al[mt], bh.x, bh.y);
            }
        }
    }

#pragma unroll
    for (int mt = 0; mt < 2; mt++) {
        int r0 = bm + wm + mt * 16 + g;
        int r1 = r0 + 8;
#pragma unroll
        for (int nt = 0; nt < 8; nt++) {
            int n0 = bn + wn + nt * 8 + tg * 2;
            float b0f = bias[n0], b1f = bias[n0 + 1];
            if (r0 < M) {
                float2 v;
                v.x = fmaxf(acc[mt][nt][0] + b0f, 0.f);
                v.y = fmaxf(acc[mt][nt][1] + b1f, 0.f);
                *(float2*)(C + (long)r0 * N + n0) = v;
            }
            if (r1 < M) {
                float2 v;
                v.x = fmaxf(acc[mt][nt][2] + b0f, 0.f);
                v.y = fmaxf(acc[mt][nt][3] + b1f, 0.f);
                *(float2*)(C + (long)r1 * N + n0) = v;
            }
        }
    }
}

// ---------------- launch ----------------
extern "C" void kernel_launch(void* const* d_in, const int* in_sizes, int n_in,
                              void* d_out, int out_size) {
    const float* x_gt   = (const float*)d_in[0];
    const float* x_ubs  = (const float*)d_in[1];
    const float* x_ag   = (const float*)d_in[2];
    const int* seen_src = (const int*)d_in[3];
    const int* seen_dst = (const int*)d_in[4];
    const int* near_src = (const int*)d_in[5];
    const int* near_dst = (const int*)d_in[6];
    const float* Ws_seen = (const float*)d_in[7];
    const float* bs_seen = (const float*)d_in[8];
    const float* Wd_seen = (const float*)d_in[9];
    const float* bd_seen = (const float*)d_in[10];
    const float* attn_seen = (const float*)d_in[11];
    const float* Wr_seen = (const float*)d_in[12];
    const float* br_seen = (const float*)d_in[13];
    const float* Ws_near = (const float*)d_in[14];
    const float* bs_near = (const float*)d_in[15];
    const float* Wd_near = (const float*)d_in[16];
    const float* bd_near = (const float*)d_in[17];
    const float* attn_near = (const float*)d_in[18];
    const float* Wr_near = (const float*)d_in[19];
    const float* br_near = (const float*)d_in[20];
    const float* W_aggr  = (const float*)d_in[21];
    const float* b_aggr  = (const float*)d_in[22];
    float* out = (float*)d_out;

    int n_gt  = in_sizes[0] / 8;
    int n_ubs = in_sizes[1] / 8;
    int n_ag  = in_sizes[2] / 16;
    int e_seen = in_sizes[3];
    int e_near = in_sizes[5];

    static cudaStream_t s2 = nullptr;
    static cudaEvent_t evFork = nullptr, evJoin = nullptr;
    if (!s2) {
        cudaStreamCreateWithFlags(&s2, cudaStreamNonBlocking);
        cudaEventCreateWithFlags(&evFork, cudaEventDisableTiming);
        cudaEventCreateWithFlags(&evJoin, cudaEventDisableTiming);
    }

    // fork: CSR chain + W prep on s2 (independent of projections)
    cudaEventRecord(evFork, 0);
    cudaStreamWaitEvent(s2, evFork, 0);

    k_wprep<<<128, 256, 0, s2>>>(W_aggr);
    k_zero<<<(2 * NAG + 255) / 256, 256, 0, s2>>>();
    k_hist<<<dim3(256, 2), 256, 0, s2>>>(seen_dst, e_seen, near_dst, e_near);
    k_assign<<<(2 * n_ag + 255) / 256, 256, 0, s2>>>(n_ag);
    k_scatter<<<dim3(256, 2), 256, 0, s2>>>(seen_dst, seen_src, e_seen,
                                            near_dst, near_src, e_near);
    cudaEventRecord(evJoin, s2);

    // projections on the main stream, concurrent with s2
    int pbx = (n_gt + 127) / 128;
    k_proj_all<<<dim3(pbx, 6), 256>>>(x_gt, x_ubs, x_ag,
        Ws_seen, bs_seen, Ws_near, bs_near,
        Wd_seen, bd_seen, Wr_seen, br_seen,
        Wd_near, bd_near, Wr_near, br_near,
        n_gt, n_ubs, n_ag);

    cudaStreamWaitEvent(0, evJoin, 0);

    k_gat<<<dim3((n_ag + 7) / 8, 2), 256>>>(attn_seen, attn_near, n_ag);

    k_gemm<<<dim3(HID / 128, (n_ag + 127) / 128), 256>>>(b_aggr, out, n_ag);
}

// round 16
// speedup vs baseline: 1.2491x; 1.0588x over previous
#include <cuda_runtime.h>
#include <cuda_bf16.h>
#include <cuda_fp16.h>

#define H 4
#define Dh 64
#define HID 256
#define NGT 100000
#define NUBS 20000
#define NAG 20000
#define ESEEN 320000
#define ENEAR 160000

typedef unsigned long long u64;
typedef unsigned int u32;

__device__ __forceinline__ u64 pk2(float lo, float hi) {
    u64 r; asm("mov.b64 %0,{%1,%2};" : "=l"(r) : "f"(lo), "f"(hi)); return r;
}
__device__ __forceinline__ u64 f2fma(u64 a, u64 b, u64 c) {
    u64 d; asm("fma.rn.f32x2 %0,%1,%2,%3;" : "=l"(d) : "l"(a), "l"(b), "l"(c)); return d;
}
__device__ __forceinline__ float2 upk2(u64 v) {
    float2 r; asm("mov.b64 {%0,%1},%2;" : "=f"(r.x), "=f"(r.y) : "l"(v)); return r;
}

__device__ __forceinline__ void bfsplit(float v, unsigned short& h, unsigned short& l) {
    __nv_bfloat16 hb = __float2bfloat16_rn(v);
    h = __bfloat16_as_ushort(hb);
    float r = v - __bfloat162float(hb);
    l = __bfloat16_as_ushort(__float2bfloat16_rn(r));
}

__device__ __forceinline__ void mma_bf16(float* d, const u32* a, u32 b0, u32 b1) {
    asm volatile(
        "mma.sync.aligned.m16n8k16.row.col.f32.bf16.bf16.f32 "
        "{%0,%1,%2,%3},{%4,%5,%6,%7},{%8,%9},{%0,%1,%2,%3};"
        : "+f"(d[0]), "+f"(d[1]), "+f"(d[2]), "+f"(d[3])
        : "r"(a[0]), "r"(a[1]), "r"(a[2]), "r"(a[3]), "r"(b0), "r"(b1));
}

// ---------------- scratch (device globals, no runtime alloc) ----------------
__device__ __half g_fs16[(NGT + NUBS) * HID];   // fs in fp16 (gathered operand)
__device__ float  g_feat[4 * NAG * HID];        // agent-side projections, fp32
__device__ u32    g_xh[NAG * 256];
__device__ u32    g_xl[NAG * 256];
__device__ uint2  g_wfh[32 * 256 * 4];
__device__ uint2  g_wfl[32 * 256 * 4];
__device__ int    g_cnt[2 * NAG];
__device__ int    g_cur[2 * NAG];
__device__ int    g_off[2 * NAG];
__device__ int    g_base[2];
__device__ int    g_perm[ESEEN + ENEAR];

#define FS_SEEN 0L
#define FS_NEAR ((long)NGT * HID)
#define FD_S    0L
#define RES_S   ((long)NAG * HID)
#define FD_N    ((long)2 * NAG * HID)
#define RES_N   ((long)3 * NAG * HID)

__global__ void k_zero() {
    int i = blockIdx.x * blockDim.x + threadIdx.x;
    if (i < 2 * NAG) g_cnt[i] = 0;
    if (i < 2) g_base[i] = 0;
}

// ---------------- W_aggr -> bf16 hi/lo in B-fragment layout ----------------
__global__ void k_wprep(const float* __restrict__ W) {
    int t = blockIdx.x * 256 + threadIdx.x;
    if (t >= 32 * 256 * 4) return;
    int ks = t >> 10, rem = t & 1023;
    int n = rem >> 2, tg = rem & 3;
    int k0 = ks * 16 + tg * 2;
    float v0 = W[(k0 + 0) * HID + n], v1 = W[(k0 + 1) * HID + n];
    float v2 = W[(k0 + 8) * HID + n], v3 = W[(k0 + 9) * HID + n];
    unsigned short h0, l0, h1, l1, h2, l2, h3, l3;
    bfsplit(v0, h0, l0); bfsplit(v1, h1, l1);
    bfsplit(v2, h2, l2); bfsplit(v3, h3, l3);
    g_wfh[t] = make_uint2((u32)h0 | ((u32)h1 << 16), (u32)h2 | ((u32)h3 << 16));
    g_wfl[t] = make_uint2((u32)l0 | ((u32)l1 << 16), (u32)l2 | ((u32)l3 << 16));
}

// ---------------- fused projections ----------------
// FP16OUT=true -> write half2 to g_fs16; else fp32 to g_feat.
template<int F, bool FP16OUT>
__device__ __forceinline__ void proj_body(const float* __restrict__ x,
                                          const float* __restrict__ W,
                                          const float* __restrict__ b,
                                          int n, long out_off) {
    int node0 = blockIdx.x * 128;
    if (node0 >= n) return;
    __shared__ float sx[128 * 16];
    int cnt = n - node0; if (cnt > 128) cnt = 128;
    int nf4 = (cnt * F) >> 2;
    for (int i = threadIdx.x; i < nf4; i += 256)
        *(float4*)(sx + i * 4) = *(const float4*)(x + (long)node0 * F + i * 4);
    __syncthreads();

    int warp = threadIdx.x >> 5, lane = threadIdx.x & 31;
    int c = (warp & 3) * 64 + (lane << 1);
    int nh = (warp >> 2) * 64;
    u64 wp[F];
#pragma unroll
    for (int k = 0; k < F; k++) wp[k] = *(const u64*)(W + k * HID + c);
    u64 bp = *(const u64*)(b + c);

    int jend = nh + 64; if (jend > cnt) jend = cnt;
#pragma unroll 1
    for (int j = nh; j < jend; j++) {
        const float* xr = sx + j * F;
        u64 acc = bp;
#pragma unroll
        for (int k4 = 0; k4 < F; k4 += 4) {
            float4 xv = *(const float4*)(xr + k4);
            acc = f2fma(pk2(xv.x, xv.x), wp[k4 + 0], acc);
            acc = f2fma(pk2(xv.y, xv.y), wp[k4 + 1], acc);
            acc = f2fma(pk2(xv.z, xv.z), wp[k4 + 2], acc);
            acc = f2fma(pk2(xv.w, xv.w), wp[k4 + 3], acc);
        }
        if (FP16OUT) {
            float2 f = upk2(acc);
            __half2 hv = __floats2half2_rn(f.x, f.y);
            *(u32*)((__half*)g_fs16 + out_off + (long)(node0 + j) * HID + c) =
                *(u32*)&hv;
        } else {
            *(u64*)(g_feat + out_off + (long)(node0 + j) * HID + c) = acc;
        }
    }
}

__global__ void k_proj_all(const float* xg, const float* xu, const float* xa,
                           const float* Wsg, const float* bsg,
                           const float* Wsu, const float* bsu,
                           const float* W0, const float* b0,
                           const float* W1, const float* b1,
                           const float* W2, const float* b2,
                           const float* W3, const float* b3,
                           int n_gt, int n_ubs, int n_ag) {
    switch (blockIdx.y) {
        case 0: proj_body<8, true>(xg, Wsg, bsg, n_gt, FS_SEEN); break;
        case 1: proj_body<8, true>(xu, Wsu, bsu, n_ubs, FS_NEAR); break;
        case 2: proj_body<16, false>(xa, W0, b0, n_ag, FD_S);  break;
        case 3: proj_body<16, false>(xa, W1, b1, n_ag, RES_S); break;
        case 4: proj_body<16, false>(xa, W2, b2, n_ag, FD_N);  break;
        default: proj_body<16, false>(xa, W3, b3, n_ag, RES_N); break;
    }
}

// ---------------- CSR build ----------------
__global__ void k_hist(const int* __restrict__ dA, int eA,
                       const int* __restrict__ dB, int eB) {
    int g = blockIdx.y;
    const int* dst = g ? dB : dA;
    int e = g ? eB : eA;
    int co = g ? NAG : 0;
    for (int i = blockIdx.x * blockDim.x + threadIdx.x; i < e;
         i += gridDim.x * blockDim.x)
        atomicAdd(&g_cnt[co + __ldg(dst + i)], 1);
}

__global__ void k_assign(int n) {
    int i = blockIdx.x * blockDim.x + threadIdx.x;
    if (i >= 2 * n) return;
    int g = (i >= n) ? 1 : 0;
    int lane = threadIdx.x & 31;
    int c = g_cnt[i];
    int pre = c;
#pragma unroll
    for (int o = 1; o < 32; o <<= 1) {
        int v = __shfl_up_sync(0xffffffffu, pre, o);
        if (lane >= o) pre += v;
    }
    int total = __shfl_sync(0xffffffffu, pre, 31);
    int excl = pre - c;
    int base = 0;
    if (lane == 31) base = atomicAdd(&g_base[g], total);
    base = __shfl_sync(0xffffffffu, base, 31);
    g_off[i] = base + excl;
    g_cur[i] = base + excl;
}

__global__ void k_scatter(const int* __restrict__ dA, const int* __restrict__ sA, int eA,
                          const int* __restrict__ dB, const int* __restrict__ sB, int eB) {
    int g = blockIdx.y;
    const int* dst = g ? dB : dA;
    const int* src = g ? sB : sA;
    int e = g ? eB : eA;
    int pb = g ? ESEEN : 0;
    for (int i = blockIdx.x * blockDim.x + threadIdx.x; i < e;
         i += gridDim.x * blockDim.x) {
        int p = atomicAdd(&g_cur[g * NAG + __ldg(dst + i)], 1);
        g_perm[pb + p] = __ldg(src + i);
    }
}

// ---------------- GATv2: one warp per dst, all 4 heads; fp16 fs gathers ---------
__device__ __forceinline__ float lrelu(float v) { return (v >= 0.f) ? v : 0.2f * v; }

__device__ __forceinline__ float escore(float4 fa, float4 fb, float4 d0, float4 d1,
                                        float4 a0, float4 a1) {
    float p;
    p = lrelu(fa.x + d0.x) * a0.x;
    p = fmaf(lrelu(fa.y + d0.y), a0.y, p);
    p = fmaf(lrelu(fa.z + d0.z), a0.z, p);
    p = fmaf(lrelu(fa.w + d0.w), a0.w, p);
    p = fmaf(lrelu(fb.x + d1.x), a1.x, p);
    p = fmaf(lrelu(fb.y + d1.y), a1.y, p);
    p = fmaf(lrelu(fb.z + d1.z), a1.z, p);
    p = fmaf(lrelu(fb.w + d1.w), a1.w, p);
    return p;
}

__device__ __forceinline__ void unpack8(uint4 q, float4& fa, float4& fb) {
    float2 v0 = __half22float2(*(const __half2*)&q.x);
    float2 v1 = __half22float2(*(const __half2*)&q.y);
    float2 v2 = __half22float2(*(const __half2*)&q.z);
    float2 v3 = __half22float2(*(const __half2*)&q.w);
    fa = make_float4(v0.x, v0.y, v1.x, v1.y);
    fb = make_float4(v2.x, v2.y, v3.x, v3.y);
}

__global__ void __launch_bounds__(256) k_gat(const float* __restrict__ attnS,
                                             const float* __restrict__ attnN, int nag) {
    int g = blockIdx.y;
    const float* attn = g ? attnN : attnS;
    long fs_off  = g ? FS_NEAR : FS_SEEN;
    long fd_off  = g ? FD_N    : FD_S;
    long res_off = g ? RES_N   : RES_S;
    int gbase    = g ? NAG : 0;
    int pb       = g ? ESEEN : 0;
    int xoff     = g ? HID : 0;

    int warp = threadIdx.x >> 5, lane = threadIdx.x & 31;
    int dstn = blockIdx.x * 8 + warp;
    if (dstn >= nag) return;
    int off = lane * 8;

    float4 a0 = __ldg((const float4*)(attn + off));
    float4 a1 = __ldg((const float4*)(attn + off + 4));
    const float* fdr = g_feat + fd_off + (long)dstn * HID + off;
    float4 d0 = *(const float4*)(fdr);
    float4 d1 = *(const float4*)(fdr + 4);
    const float* rvr = g_feat + res_off + (long)dstn * HID + off;
    float4 r0 = *(const float4*)(rvr);
    float4 r1 = *(const float4*)(rvr + 4);

    int e0 = g_off[gbase + dstn];
    int e1 = e0 + g_cnt[gbase + dstn];
    const __half* fs = g_fs16 + fs_off;
    const int* pp = g_perm + pb;

    int id0 = 0, id1 = 0, id2 = 0, id3 = 0;
    if (e0 < e1) {
        int rr = e1 - e0;
        id0 = pp[e0];
        id1 = (rr > 1) ? pp[e0 + 1] : id0;
        id2 = (rr > 2) ? pp[e0 + 2] : id0;
        id3 = (rr > 3) ? pp[e0 + 3] : id0;
    }

    float mx = -3.0e38f, den = 0.f;
    float4 acc0 = make_float4(0.f, 0.f, 0.f, 0.f), acc1 = acc0;

    for (int i = e0; i < e1; i += 4) {
        // one 16B load per edge per lane (8 halfs)
        uint4 q0 = __ldg((const uint4*)(fs + (long)id0 * HID + off));
        uint4 q1 = __ldg((const uint4*)(fs + (long)id1 * HID + off));
        uint4 q2 = __ldg((const uint4*)(fs + (long)id2 * HID + off));
        uint4 q3 = __ldg((const uint4*)(fs + (long)id3 * HID + off));

        // prefetch next chunk's ids while gathers are in flight
        if (i + 4 < e1) {
            int j = i + 4, rr = e1 - j;
            id0 = pp[j];
            id1 = (rr > 1) ? pp[j + 1] : id0;
            id2 = (rr > 2) ? pp[j + 2] : id0;
            id3 = (rr > 3) ? pp[j + 3] : id0;
        }

        float4 f0a, f0b, f1a, f1b, f2a, f2b, f3a, f3b;
        unpack8(q0, f0a, f0b);
        unpack8(q1, f1a, f1b);
        unpack8(q2, f2a, f2b);
        unpack8(q3, f3a, f3b);

        float p0 = escore(f0a, f0b, d0, d1, a0, a1);
        float p1 = escore(f1a, f1b, d0, d1, a0, a1);
        float p2 = escore(f2a, f2b, d0, d1, a0, a1);
        float p3 = escore(f3a, f3b, d0, d1, a0, a1);
#pragma unroll
        for (int o = 1; o < 8; o <<= 1) {
            p0 += __shfl_xor_sync(0xffffffffu, p0, o);
            p1 += __shfl_xor_sync(0xffffffffu, p1, o);
            p2 += __shfl_xor_sync(0xffffffffu, p2, o);
            p3 += __shfl_xor_sync(0xffffffffu, p3, o);
        }
        int r = e1 - i;
        if (r < 2) p1 = -3.0e38f;
        if (r < 3) p2 = -3.0e38f;
        if (r < 4) p3 = -3.0e38f;

        float cm = fmaxf(fmaxf(p0, p1), fmaxf(p2, p3));
        float nmx = fmaxf(mx, cm);
        float scale = __expf(mx - nmx);
        float x0 = __expf(p0 - nmx);
        float x1 = __expf(p1 - nmx);
        float x2 = __expf(p2 - nmx);
        float x3 = __expf(p3 - nmx);
        den = fmaf(den, scale, (x0 + x1) + (x2 + x3));
        acc0.x = fmaf(acc0.x, scale, fmaf(x0, f0a.x, fmaf(x1, f1a.x, fmaf(x2, f2a.x, x3 * f3a.x))));
        acc0.y = fmaf(acc0.y, scale, fmaf(x0, f0a.y, fmaf(x1, f1a.y, fmaf(x2, f2a.y, x3 * f3a.y))));
        acc0.z = fmaf(acc0.z, scale, fmaf(x0, f0a.z, fmaf(x1, f1a.z, fmaf(x2, f2a.z, x3 * f3a.z))));
        acc0.w = fmaf(acc0.w, scale, fmaf(x0, f0a.w, fmaf(x1, f1a.w, fmaf(x2, f2a.w, x3 * f3a.w))));
        acc1.x = fmaf(acc1.x, scale, fmaf(x0, f0b.x, fmaf(x1, f1b.x, fmaf(x2, f2b.x, x3 * f3b.x))));
        acc1.y = fmaf(acc1.y, scale, fmaf(x0, f0b.y, fmaf(x1, f1b.y, fmaf(x2, f2b.y, x3 * f3b.y))));
        acc1.z = fmaf(acc1.z, scale, fmaf(x0, f0b.z, fmaf(x1, f1b.z, fmaf(x2, f2b.z, x3 * f3b.z))));
        acc1.w = fmaf(acc1.w, scale, fmaf(x0, f0b.w, fmaf(x1, f1b.w, fmaf(x2, f2b.w, x3 * f3b.w))));
        mx = nmx;
    }
    float inv = (e1 == e0) ? 1.f : (1.f / den);
    float o[8];
    o[0] = fmaxf(fmaf(acc0.x, inv, r0.x), 0.f);
    o[1] = fmaxf(fmaf(acc0.y, inv, r0.y), 0.f);
    o[2] = fmaxf(fmaf(acc0.z, inv, r0.z), 0.f);
    o[3] = fmaxf(fmaf(acc0.w, inv, r0.w), 0.f);
    o[4] = fmaxf(fmaf(acc1.x, inv, r1.x), 0.f);
    o[5] = fmaxf(fmaf(acc1.y, inv, r1.y), 0.f);
    o[6] = fmaxf(fmaf(acc1.z, inv, r1.z), 0.f);
    o[7] = fmaxf(fmaf(acc1.w, inv, r1.w), 0.f);
    u32 hp[4], lp[4];
#pragma unroll
    for (int j = 0; j < 4; j++) {
        unsigned short h0, l0, h1, l1;
        bfsplit(o[2 * j], h0, l0);
        bfsplit(o[2 * j + 1], h1, l1);
        hp[j] = (u32)h0 | ((u32)h1 << 16);
        lp[j] = (u32)l0 | ((u32)l1 << 16);
    }
    int pidx = dstn * 256 + (xoff >> 1) + lane * 4;
    *(uint4*)(g_xh + pidx) = make_uint4(hp[0], hp[1], hp[2], hp[3]);
    *(uint4*)(g_xl + pidx) = make_uint4(lp[0], lp[1], lp[2], lp[3]);
}

// ---------------- final GEMM via split-bf16 mma.sync ----------------
__global__ void __launch_bounds__(256) k_gemm(const float* __restrict__ bias,
                                              float* __restrict__ C, int M) {
    const int N = HID;
    int warp = threadIdx.x >> 5, lane = threadIdx.x & 31;
    int g = lane >> 2, tg = lane & 3;
    int bm = blockIdx.y * 128, bn = blockIdx.x * 128;
    int wm = (warp >> 1) * 32, wn = (warp & 1) * 64;

    float acc[2][8][4];
#pragma unroll
    for (int mt = 0; mt < 2; mt++)
#pragma unroll
        for (int nt = 0; nt < 8; nt++)
#pragma unroll
            for (int q = 0; q < 4; q++) acc[mt][nt][q] = 0.f;

#pragma unroll 1
    for (int ks = 0; ks < 32; ks++) {
        u32 ah[2][4], al[2][4];
        int pb = ks * 8 + tg;
#pragma unroll
        for (int mt = 0; mt < 2; mt++) {
            int r0 = bm + wm + mt * 16 + g;
            int r1 = r0 + 8;
            if (r0 > M - 1) r0 = M - 1;
            if (r1 > M - 1) r1 = M - 1;
            ah[mt][0] = g_xh[r0 * 256 + pb];
            ah[mt][1] = g_xh[r1 * 256 + pb];
            ah[mt][2] = g_xh[r0 * 256 + pb + 4];
            ah[mt][3] = g_xh[r1 * 256 + pb + 4];
            al[mt][0] = g_xl[r0 * 256 + pb];
            al[mt][1] = g_xl[r1 * 256 + pb];
            al[mt][2] = g_xl[r0 * 256 + pb + 4];
            al[mt][3] = g_xl[r1 * 256 + pb + 4];
        }
        const uint2* wh = g_wfh + (ks * 256 + bn + wn) * 4 + lane;
        const uint2* wl = g_wfl + (ks * 256 + bn + wn) * 4 + lane;
#pragma unroll
        for (int nt = 0; nt < 8; nt++) {
            uint2 bh = __ldg(wh + nt * 32);
            uint2 bl = __ldg(wl + nt * 32);
#pragma unroll
            for (int mt = 0; mt < 2; mt++) {
                mma_bf16(acc[mt][nt], ah[mt], bh.x, bh.y);
                mma_bf16(acc[mt][nt], ah[mt], bl.x, bl.y);
                mma_bf16(acc[mt][nt], al[mt], bh.x, bh.y);
            }
        }
    }

#pragma unroll
    for (int mt = 0; mt < 2; mt++) {
        int r0 = bm + wm + mt * 16 + g;
        int r1 = r0 + 8;
#pragma unroll
        for (int nt = 0; nt < 8; nt++) {
            int n0 = bn + wn + nt * 8 + tg * 2;
            float b0f = bias[n0], b1f = bias[n0 + 1];
            if (r0 < M) {
                float2 v;
                v.x = fmaxf(acc[mt][nt][0] + b0f, 0.f);
                v.y = fmaxf(acc[mt][nt][1] + b1f, 0.f);
                *(float2*)(C + (long)r0 * N + n0) = v;
            }
            if (r1 < M) {
                float2 v;
                v.x = fmaxf(acc[mt][nt][2] + b0f, 0.f);
                v.y = fmaxf(acc[mt][nt][3] + b1f, 0.f);
                *(float2*)(C + (long)r1 * N + n0) = v;
            }
        }
    }
}

// ---------------- launch ----------------
extern "C" void kernel_launch(void* const* d_in, const int* in_sizes, int n_in,
                              void* d_out, int out_size) {
    const float* x_gt   = (const float*)d_in[0];
    const float* x_ubs  = (const float*)d_in[1];
    const float* x_ag   = (const float*)d_in[2];
    const int* seen_src = (const int*)d_in[3];
    const int* seen_dst = (const int*)d_in[4];
    const int* near_src = (const int*)d_in[5];
    const int* near_dst = (const int*)d_in[6];
    const float* Ws_seen = (const float*)d_in[7];
    const float* bs_seen = (const float*)d_in[8];
    const float* Wd_seen = (const float*)d_in[9];
    const float* bd_seen = (const float*)d_in[10];
    const float* attn_seen = (const float*)d_in[11];
    const float* Wr_seen = (const float*)d_in[12];
    const float* br_seen = (const float*)d_in[13];
    const float* Ws_near = (const float*)d_in[14];
    const float* bs_near = (const float*)d_in[15];
    const float* Wd_near = (const float*)d_in[16];
    const float* bd_near = (const float*)d_in[17];
    const float* attn_near = (const float*)d_in[18];
    const float* Wr_near = (const float*)d_in[19];
    const float* br_near = (const float*)d_in[20];
    const float* W_aggr  = (const float*)d_in[21];
    const float* b_aggr  = (const float*)d_in[22];
    float* out = (float*)d_out;

    int n_gt  = in_sizes[0] / 8;
    int n_ubs = in_sizes[1] / 8;
    int n_ag  = in_sizes[2] / 16;
    int e_seen = in_sizes[3];
    int e_near = in_sizes[5];

    static cudaStream_t s2 = nullptr;
    static cudaEvent_t evFork = nullptr, evJoin = nullptr;
    if (!s2) {
        cudaStreamCreateWithFlags(&s2, cudaStreamNonBlocking);
        cudaEventCreateWithFlags(&evFork, cudaEventDisableTiming);
        cudaEventCreateWithFlags(&evJoin, cudaEventDisableTiming);
    }

    // fork: CSR chain + W prep on s2 (independent of projections)
    cudaEventRecord(evFork, 0);
    cudaStreamWaitEvent(s2, evFork, 0);

    k_wprep<<<128, 256, 0, s2>>>(W_aggr);
    k_zero<<<(2 * NAG + 255) / 256, 256, 0, s2>>>();
    k_hist<<<dim3(256, 2), 256, 0, s2>>>(seen_dst, e_seen, near_dst, e_near);
    k_assign<<<(2 * n_ag + 255) / 256, 256, 0, s2>>>(n_ag);
    k_scatter<<<dim3(256, 2), 256, 0, s2>>>(seen_dst, seen_src, e_seen,
                                            near_dst, near_src, e_near);
    cudaEventRecord(evJoin, s2);

    // projections on the main stream, concurrent with s2
    int pbx = (n_gt + 127) / 128;
    k_proj_all<<<dim3(pbx, 6), 256>>>(x_gt, x_ubs, x_ag,
        Ws_seen, bs_seen, Ws_near, bs_near,
        Wd_seen, bd_seen, Wr_seen, br_seen,
        Wd_near, bd_near, Wr_near, br_near,
        n_gt, n_ubs, n_ag);

    cudaStreamWaitEvent(0, evJoin, 0);

    k_gat<<<dim3((n_ag + 7) / 8, 2), 256>>>(attn_seen, attn_near, n_ag);

    k_gemm<<<dim3(HID / 128, (n_ag + 127) / 128), 256>>>(b_aggr, out, n_ag);
}

// round 17
// speedup vs baseline: 1.3023x; 1.0425x over previous
#include <cuda_runtime.h>
#include <cuda_bf16.h>
#include <cuda_fp16.h>

#define H 4
#define Dh 64
#define HID 256
#define NGT 100000
#define NUBS 20000
#define NAG 20000
#define ESEEN 320000
#define ENEAR 160000

typedef unsigned long long u64;
typedef unsigned int u32;

__device__ __forceinline__ u64 pk2(float lo, float hi) {
    u64 r; asm("mov.b64 %0,{%1,%2};" : "=l"(r) : "f"(lo), "f"(hi)); return r;
}
__device__ __forceinline__ u64 f2fma(u64 a, u64 b, u64 c) {
    u64 d; asm("fma.rn.f32x2 %0,%1,%2,%3;" : "=l"(d) : "l"(a), "l"(b), "l"(c)); return d;
}
__device__ __forceinline__ float2 upk2(u64 v) {
    float2 r; asm("mov.b64 {%0,%1},%2;" : "=f"(r.x), "=f"(r.y) : "l"(v)); return r;
}

__device__ __forceinline__ void bfsplit(float v, unsigned short& h, unsigned short& l) {
    __nv_bfloat16 hb = __float2bfloat16_rn(v);
    h = __bfloat16_as_ushort(hb);
    float r = v - __bfloat162float(hb);
    l = __bfloat16_as_ushort(__float2bfloat16_rn(r));
}

__device__ __forceinline__ void mma_bf16(float* d, const u32* a, u32 b0, u32 b1) {
    asm volatile(
        "mma.sync.aligned.m16n8k16.row.col.f32.bf16.bf16.f32 "
        "{%0,%1,%2,%3},{%4,%5,%6,%7},{%8,%9},{%0,%1,%2,%3};"
        : "+f"(d[0]), "+f"(d[1]), "+f"(d[2]), "+f"(d[3])
        : "r"(a[0]), "r"(a[1]), "r"(a[2]), "r"(a[3]), "r"(b0), "r"(b1));
}

// ---------------- scratch (device globals, no runtime alloc) ----------------
__device__ __half g_fs16[(NGT + NUBS) * HID];   // fs in fp16 (gathered operand)
__device__ float  g_feat[4 * NAG * HID];        // agent-side projections, fp32
__device__ u32    g_xh[NAG * 256];
__device__ u32    g_xl[NAG * 256];
__device__ uint2  g_wfh[32 * 256 * 4];
__device__ uint2  g_wfl[32 * 256 * 4];
__device__ int    g_cnt[2 * NAG];
__device__ int    g_cur[2 * NAG];
__device__ int    g_off[2 * NAG];
__device__ int    g_base[2];
__device__ int    g_perm[ESEEN + ENEAR];

#define FS_SEEN 0L
#define FS_NEAR ((long)NGT * HID)
#define FD_S    0L
#define RES_S   ((long)NAG * HID)
#define FD_N    ((long)2 * NAG * HID)
#define RES_N   ((long)3 * NAG * HID)

// ---------------- fused zero + W_aggr bf16-split prep ----------------
__global__ void k_zero_wprep(const float* __restrict__ W) {
    int t = blockIdx.x * 256 + threadIdx.x;
    if (t < 2 * NAG) g_cnt[t] = 0;
    if (t < 2) g_base[t] = 0;
    if (t < 32 * 256 * 4) {
        int ks = t >> 10, rem = t & 1023;
        int n = rem >> 2, tg = rem & 3;
        int k0 = ks * 16 + tg * 2;
        float v0 = W[(k0 + 0) * HID + n], v1 = W[(k0 + 1) * HID + n];
        float v2 = W[(k0 + 8) * HID + n], v3 = W[(k0 + 9) * HID + n];
        unsigned short h0, l0, h1, l1, h2, l2, h3, l3;
        bfsplit(v0, h0, l0); bfsplit(v1, h1, l1);
        bfsplit(v2, h2, l2); bfsplit(v3, h3, l3);
        g_wfh[t] = make_uint2((u32)h0 | ((u32)h1 << 16), (u32)h2 | ((u32)h3 << 16));
        g_wfl[t] = make_uint2((u32)l0 | ((u32)l1 << 16), (u32)l2 | ((u32)l3 << 16));
    }
}

// ---------------- fused projections ----------------
template<int F, bool FP16OUT>
__device__ __forceinline__ void proj_body(const float* __restrict__ x,
                                          const float* __restrict__ W,
                                          const float* __restrict__ b,
                                          int n, long out_off) {
    int node0 = blockIdx.x * 128;
    if (node0 >= n) return;
    __shared__ float sx[128 * 16];
    int cnt = n - node0; if (cnt > 128) cnt = 128;
    int nf4 = (cnt * F) >> 2;
    for (int i = threadIdx.x; i < nf4; i += 256)
        *(float4*)(sx + i * 4) = *(const float4*)(x + (long)node0 * F + i * 4);
    __syncthreads();

    int warp = threadIdx.x >> 5, lane = threadIdx.x & 31;
    int c = (warp & 3) * 64 + (lane << 1);
    int nh = (warp >> 2) * 64;
    u64 wp[F];
#pragma unroll
    for (int k = 0; k < F; k++) wp[k] = *(const u64*)(W + k * HID + c);
    u64 bp = *(const u64*)(b + c);

    int jend = nh + 64; if (jend > cnt) jend = cnt;
#pragma unroll 1
    for (int j = nh; j < jend; j++) {
        const float* xr = sx + j * F;
        u64 acc = bp;
#pragma unroll
        for (int k4 = 0; k4 < F; k4 += 4) {
            float4 xv = *(const float4*)(xr + k4);
            acc = f2fma(pk2(xv.x, xv.x), wp[k4 + 0], acc);
            acc = f2fma(pk2(xv.y, xv.y), wp[k4 + 1], acc);
            acc = f2fma(pk2(xv.z, xv.z), wp[k4 + 2], acc);
            acc = f2fma(pk2(xv.w, xv.w), wp[k4 + 3], acc);
        }
        if (FP16OUT) {
            float2 f = upk2(acc);
            __half2 hv = __floats2half2_rn(f.x, f.y);
            *(u32*)((__half*)g_fs16 + out_off + (long)(node0 + j) * HID + c) =
                *(u32*)&hv;
        } else {
            *(u64*)(g_feat + out_off + (long)(node0 + j) * HID + c) = acc;
        }
    }
}

__global__ void k_proj_all(const float* xg, const float* xu, const float* xa,
                           const float* Wsg, const float* bsg,
                           const float* Wsu, const float* bsu,
                           const float* W0, const float* b0,
                           const float* W1, const float* b1,
                           const float* W2, const float* b2,
                           const float* W3, const float* b3,
                           int n_gt, int n_ubs, int n_ag) {
    switch (blockIdx.y) {
        case 0: proj_body<8, true>(xg, Wsg, bsg, n_gt, FS_SEEN); break;
        case 1: proj_body<8, true>(xu, Wsu, bsu, n_ubs, FS_NEAR); break;
        case 2: proj_body<16, false>(xa, W0, b0, n_ag, FD_S);  break;
        case 3: proj_body<16, false>(xa, W1, b1, n_ag, RES_S); break;
        case 4: proj_body<16, false>(xa, W2, b2, n_ag, FD_N);  break;
        default: proj_body<16, false>(xa, W3, b3, n_ag, RES_N); break;
    }
}

// ---------------- CSR build ----------------
__global__ void k_hist(const int* __restrict__ dA, int eA,
                       const int* __restrict__ dB, int eB) {
    int g = blockIdx.y;
    const int* dst = g ? dB : dA;
    int e = g ? eB : eA;
    int co = g ? NAG : 0;
    for (int i = blockIdx.x * blockDim.x + threadIdx.x; i < e;
         i += gridDim.x * blockDim.x)
        atomicAdd(&g_cnt[co + __ldg(dst + i)], 1);
}

__global__ void k_assign(int n) {
    int i = blockIdx.x * blockDim.x + threadIdx.x;
    if (i >= 2 * n) return;
    int g = (i >= n) ? 1 : 0;
    int lane = threadIdx.x & 31;
    int c = g_cnt[i];
    int pre = c;
#pragma unroll
    for (int o = 1; o < 32; o <<= 1) {
        int v = __shfl_up_sync(0xffffffffu, pre, o);
        if (lane >= o) pre += v;
    }
    int total = __shfl_sync(0xffffffffu, pre, 31);
    int excl = pre - c;
    int base = 0;
    if (lane == 31) base = atomicAdd(&g_base[g], total);
    base = __shfl_sync(0xffffffffu, base, 31);
    g_off[i] = base + excl;
    g_cur[i] = base + excl;
}

__global__ void k_scatter(const int* __restrict__ dA, const int* __restrict__ sA, int eA,
                          const int* __restrict__ dB, const int* __restrict__ sB, int eB) {
    int g = blockIdx.y;
    const int* dst = g ? dB : dA;
    const int* src = g ? sB : sA;
    int e = g ? eB : eA;
    int pb = g ? ESEEN : 0;
    for (int i = blockIdx.x * blockDim.x + threadIdx.x; i < e;
         i += gridDim.x * blockDim.x) {
        int p = atomicAdd(&g_cur[g * NAG + __ldg(dst + i)], 1);
        g_perm[pb + p] = __ldg(src + i);
    }
}

// ---------------- GATv2: fp16 gathers, 2-deep row pipeline ----------------
__device__ __forceinline__ float lrelu(float v) { return (v >= 0.f) ? v : 0.2f * v; }

__device__ __forceinline__ float escore(float4 fa, float4 fb, float4 d0, float4 d1,
                                        float4 a0, float4 a1) {
    float p;
    p = lrelu(fa.x + d0.x) * a0.x;
    p = fmaf(lrelu(fa.y + d0.y), a0.y, p);
    p = fmaf(lrelu(fa.z + d0.z), a0.z, p);
    p = fmaf(lrelu(fa.w + d0.w), a0.w, p);
    p = fmaf(lrelu(fb.x + d1.x), a1.x, p);
    p = fmaf(lrelu(fb.y + d1.y), a1.y, p);
    p = fmaf(lrelu(fb.z + d1.z), a1.z, p);
    p = fmaf(lrelu(fb.w + d1.w), a1.w, p);
    return p;
}

__device__ __forceinline__ void unpack8(uint4 q, float4& fa, float4& fb) {
    float2 v0 = __half22float2(*(const __half2*)&q.x);
    float2 v1 = __half22float2(*(const __half2*)&q.y);
    float2 v2 = __half22float2(*(const __half2*)&q.z);
    float2 v3 = __half22float2(*(const __half2*)&q.w);
    fa = make_float4(v0.x, v0.y, v1.x, v1.y);
    fb = make_float4(v2.x, v2.y, v3.x, v3.y);
}

__global__ void __launch_bounds__(256) k_gat(const float* __restrict__ attnS,
                                             const float* __restrict__ attnN, int nag) {
    int g = blockIdx.y;
    const float* attn = g ? attnN : attnS;
    long fs_off  = g ? FS_NEAR : FS_SEEN;
    long fd_off  = g ? FD_N    : FD_S;
    long res_off = g ? RES_N   : RES_S;
    int gbase    = g ? NAG : 0;
    int pb       = g ? ESEEN : 0;
    int xoff     = g ? HID : 0;

    int warp = threadIdx.x >> 5, lane = threadIdx.x & 31;
    int dstn = blockIdx.x * 8 + warp;
    if (dstn >= nag) return;
    int off = lane * 8;

    float4 a0 = __ldg((const float4*)(attn + off));
    float4 a1 = __ldg((const float4*)(attn + off + 4));
    const float* fdr = g_feat + fd_off + (long)dstn * HID + off;
    float4 d0 = *(const float4*)(fdr);
    float4 d1 = *(const float4*)(fdr + 4);
    const float* rvr = g_feat + res_off + (long)dstn * HID + off;
    float4 r0 = *(const float4*)(rvr);
    float4 r1 = *(const float4*)(rvr + 4);

    int e0 = g_off[gbase + dstn];
    int e1 = e0 + g_cnt[gbase + dstn];
    const __half* fs = g_fs16 + fs_off;
    const int* pp = g_perm + pb;

    int ib4[4];
    auto ldids = [&](int j, int* o) {
        int rr = e1 - j;
        o[0] = pp[j];
        o[1] = (rr > 1) ? pp[j + 1] : o[0];
        o[2] = (rr > 2) ? pp[j + 2] : o[0];
        o[3] = (rr > 3) ? pp[j + 3] : o[0];
    };
    uint4 q0, q1, q2, q3;
    auto ldrows = [&](const int* id, uint4& a, uint4& b, uint4& c, uint4& d) {
        a = __ldg((const uint4*)(fs + (long)id[0] * HID + off));
        b = __ldg((const uint4*)(fs + (long)id[1] * HID + off));
        c = __ldg((const uint4*)(fs + (long)id[2] * HID + off));
        d = __ldg((const uint4*)(fs + (long)id[3] * HID + off));
    };
    if (e0 < e1) {
        int ia4[4];
        ldids(e0, ia4);
        ldrows(ia4, q0, q1, q2, q3);
        if (e0 + 4 < e1) ldids(e0 + 4, ib4);
    }

    float mx = -3.0e38f, den = 0.f;
    float4 acc0 = make_float4(0.f, 0.f, 0.f, 0.f), acc1 = acc0;

    for (int i = e0; i < e1; i += 4) {
        // issue next chunk's rows BEFORE consuming current (2-deep pipeline)
        bool more = (i + 4 < e1);
        uint4 n0, n1, n2, n3;
        if (more) ldrows(ib4, n0, n1, n2, n3);
        if (i + 8 < e1) ldids(i + 8, ib4);

        float4 f0a, f0b, f1a, f1b, f2a, f2b, f3a, f3b;
        unpack8(q0, f0a, f0b);
        unpack8(q1, f1a, f1b);
        unpack8(q2, f2a, f2b);
        unpack8(q3, f3a, f3b);

        float p0 = escore(f0a, f0b, d0, d1, a0, a1);
        float p1 = escore(f1a, f1b, d0, d1, a0, a1);
        float p2 = escore(f2a, f2b, d0, d1, a0, a1);
        float p3 = escore(f3a, f3b, d0, d1, a0, a1);
#pragma unroll
        for (int o = 1; o < 8; o <<= 1) {
            p0 += __shfl_xor_sync(0xffffffffu, p0, o);
            p1 += __shfl_xor_sync(0xffffffffu, p1, o);
            p2 += __shfl_xor_sync(0xffffffffu, p2, o);
            p3 += __shfl_xor_sync(0xffffffffu, p3, o);
        }
        int r = e1 - i;
        if (r < 2) p1 = -3.0e38f;
        if (r < 3) p2 = -3.0e38f;
        if (r < 4) p3 = -3.0e38f;

        float cm = fmaxf(fmaxf(p0, p1), fmaxf(p2, p3));
        float nmx = fmaxf(mx, cm);
        float scale = __expf(mx - nmx);
        float x0 = __expf(p0 - nmx);
        float x1 = __expf(p1 - nmx);
        float x2 = __expf(p2 - nmx);
        float x3 = __expf(p3 - nmx);
        den = fmaf(den, scale, (x0 + x1) + (x2 + x3));
        acc0.x = fmaf(acc0.x, scale, fmaf(x0, f0a.x, fmaf(x1, f1a.x, fmaf(x2, f2a.x, x3 * f3a.x))));
        acc0.y = fmaf(acc0.y, scale, fmaf(x0, f0a.y, fmaf(x1, f1a.y, fmaf(x2, f2a.y, x3 * f3a.y))));
        acc0.z = fmaf(acc0.z, scale, fmaf(x0, f0a.z, fmaf(x1, f1a.z, fmaf(x2, f2a.z, x3 * f3a.z))));
        acc0.w = fmaf(acc0.w, scale, fmaf(x0, f0a.w, fmaf(x1, f1a.w, fmaf(x2, f2a.w, x3 * f3a.w))));
        acc1.x = fmaf(acc1.x, scale, fmaf(x0, f0b.x, fmaf(x1, f1b.x, fmaf(x2, f2b.x, x3 * f3b.x))));
        acc1.y = fmaf(acc1.y, scale, fmaf(x0, f0b.y, fmaf(x1, f1b.y, fmaf(x2, f2b.y, x3 * f3b.y))));
        acc1.z = fmaf(acc1.z, scale, fmaf(x0, f0b.z, fmaf(x1, f1b.z, fmaf(x2, f2b.z, x3 * f3b.z))));
        acc1.w = fmaf(acc1.w, scale, fmaf(x0, f0b.w, fmaf(x1, f1b.w, fmaf(x2, f2b.w, x3 * f3b.w))));
        mx = nmx;
        if (more) { q0 = n0; q1 = n1; q2 = n2; q3 = n3; }
    }
    float inv = (e1 == e0) ? 1.f : (1.f / den);
    float o[8];
    o[0] = fmaxf(fmaf(acc0.x, inv, r0.x), 0.f);
    o[1] = fmaxf(fmaf(acc0.y, inv, r0.y), 0.f);
    o[2] = fmaxf(fmaf(acc0.z, inv, r0.z), 0.f);
    o[3] = fmaxf(fmaf(acc0.w, inv, r0.w), 0.f);
    o[4] = fmaxf(fmaf(acc1.x, inv, r1.x), 0.f);
    o[5] = fmaxf(fmaf(acc1.y, inv, r1.y), 0.f);
    o[6] = fmaxf(fmaf(acc1.z, inv, r1.z), 0.f);
    o[7] = fmaxf(fmaf(acc1.w, inv, r1.w), 0.f);
    u32 hp[4], lp[4];
#pragma unroll
    for (int j = 0; j < 4; j++) {
        unsigned short h0, l0, h1, l1;
        bfsplit(o[2 * j], h0, l0);
        bfsplit(o[2 * j + 1], h1, l1);
        hp[j] = (u32)h0 | ((u32)h1 << 16);
        lp[j] = (u32)l0 | ((u32)l1 << 16);
    }
    int pidx = dstn * 256 + (xoff >> 1) + lane * 4;
    *(uint4*)(g_xh + pidx) = make_uint4(hp[0], hp[1], hp[2], hp[3]);
    *(uint4*)(g_xl + pidx) = make_uint4(lp[0], lp[1], lp[2], lp[3]);
}

// ---------------- final GEMM via split-bf16 mma.sync ----------------
__global__ void __launch_bounds__(256) k_gemm(const float* __restrict__ bias,
                                              float* __restrict__ C, int M) {
    const int N = HID;
    int warp = threadIdx.x >> 5, lane = threadIdx.x & 31;
    int g = lane >> 2, tg = lane & 3;
    int bm = blockIdx.y * 128, bn = blockIdx.x * 128;
    int wm = (warp >> 1) * 32, wn = (warp & 1) * 64;

    float acc[2][8][4];
#pragma unroll
    for (int mt = 0; mt < 2; mt++)
#pragma unroll
        for (int nt = 0; nt < 8; nt++)
#pragma unroll
            for (int q = 0; q < 4; q++) acc[mt][nt][q] = 0.f;

#pragma unroll 1
    for (int ks = 0; ks < 32; ks++) {
        u32 ah[2][4], al[2][4];
        int pb = ks * 8 + tg;
#pragma unroll
        for (int mt = 0; mt < 2; mt++) {
            int r0 = bm + wm + mt * 16 + g;
            int r1 = r0 + 8;
            if (r0 > M - 1) r0 = M - 1;
            if (r1 > M - 1) r1 = M - 1;
            ah[mt][0] = g_xh[r0 * 256 + pb];
            ah[mt][1] = g_xh[r1 * 256 + pb];
            ah[mt][2] = g_xh[r0 * 256 + pb + 4];
            ah[mt][3] = g_xh[r1 * 256 + pb + 4];
            al[mt][0] = g_xl[r0 * 256 + pb];
            al[mt][1] = g_xl[r1 * 256 + pb];
            al[mt][2] = g_xl[r0 * 256 + pb + 4];
            al[mt][3] = g_xl[r1 * 256 + pb + 4];
        }
        const uint2* wh = g_wfh + (ks * 256 + bn + wn) * 4 + lane;
        const uint2* wl = g_wfl + (ks * 256 + bn + wn) * 4 + lane;
#pragma unroll
        for (int nt = 0; nt < 8; nt++) {
            uint2 bh = __ldg(wh + nt * 32);
            uint2 bl = __ldg(wl + nt * 32);
#pragma unroll
            for (int mt = 0; mt < 2; mt++) {
                mma_bf16(acc[mt][nt], ah[mt], bh.x, bh.y);
                mma_bf16(acc[mt][nt], ah[mt], bl.x, bl.y);
                mma_bf16(acc[mt][nt], al[mt], bh.x, bh.y);
            }
        }
    }

#pragma unroll
    for (int mt = 0; mt < 2; mt++) {
        int r0 = bm + wm + mt * 16 + g;
        int r1 = r0 + 8;
#pragma unroll
        for (int nt = 0; nt < 8; nt++) {
            int n0 = bn + wn + nt * 8 + tg * 2;
            float b0f = bias[n0], b1f = bias[n0 + 1];
            if (r0 < M) {
                float2 v;
                v.x = fmaxf(acc[mt][nt][0] + b0f, 0.f);
                v.y = fmaxf(acc[mt][nt][1] + b1f, 0.f);
                *(float2*)(C + (long)r0 * N + n0) = v;
            }
            if (r1 < M) {
                float2 v;
                v.x = fmaxf(acc[mt][nt][2] + b0f, 0.f);
                v.y = fmaxf(acc[mt][nt][3] + b1f, 0.f);
                *(float2*)(C + (long)r1 * N + n0) = v;
            }
        }
    }
}

// ---------------- launch ----------------
extern "C" void kernel_launch(void* const* d_in, const int* in_sizes, int n_in,
                              void* d_out, int out_size) {
    const float* x_gt   = (const float*)d_in[0];
    const float* x_ubs  = (const float*)d_in[1];
    const float* x_ag   = (const float*)d_in[2];
    const int* seen_src = (const int*)d_in[3];
    const int* seen_dst = (const int*)d_in[4];
    const int* near_src = (const int*)d_in[5];
    const int* near_dst = (const int*)d_in[6];
    const float* Ws_seen = (const float*)d_in[7];
    const float* bs_seen = (const float*)d_in[8];
    const float* Wd_seen = (const float*)d_in[9];
    const float* bd_seen = (const float*)d_in[10];
    const float* attn_seen = (const float*)d_in[11];
    const float* Wr_seen = (const float*)d_in[12];
    const float* br_seen = (const float*)d_in[13];
    const float* Ws_near = (const float*)d_in[14];
    const float* bs_near = (const float*)d_in[15];
    const float* Wd_near = (const float*)d_in[16];
    const float* bd_near = (const float*)d_in[17];
    const float* attn_near = (const float*)d_in[18];
    const float* Wr_near = (const float*)d_in[19];
    const float* br_near = (const float*)d_in[20];
    const float* W_aggr  = (const float*)d_in[21];
    const float* b_aggr  = (const float*)d_in[22];
    float* out = (float*)d_out;

    int n_gt  = in_sizes[0] / 8;
    int n_ubs = in_sizes[1] / 8;
    int n_ag  = in_sizes[2] / 16;
    int e_seen = in_sizes[3];
    int e_near = in_sizes[5];

    static cudaStream_t s2 = nullptr;
    static cudaEvent_t evFork = nullptr, evJoin = nullptr;
    if (!s2) {
        cudaStreamCreateWithFlags(&s2, cudaStreamNonBlocking);
        cudaEventCreateWithFlags(&evFork, cudaEventDisableTiming);
        cudaEventCreateWithFlags(&evJoin, cudaEventDisableTiming);
    }

    // fork: CSR chain + W prep on s2 (independent of projections)
    cudaEventRecord(evFork, 0);
    cudaStreamWaitEvent(s2, evFork, 0);

    k_zero_wprep<<<(2 * NAG + 255) / 256, 256, 0, s2>>>(W_aggr);
    k_hist<<<dim3(256, 2), 256, 0, s2>>>(seen_dst, e_seen, near_dst, e_near);
    k_assign<<<(2 * n_ag + 255) / 256, 256, 0, s2>>>(n_ag);
    k_scatter<<<dim3(256, 2), 256, 0, s2>>>(seen_dst, seen_src, e_seen,
                                            near_dst, near_src, e_near);
    cudaEventRecord(evJoin, s2);

    // projections on the main stream, concurrent with s2
    int pbx = (n_gt + 127) / 128;
    k_proj_all<<<dim3(pbx, 6), 256>>>(x_gt, x_ubs, x_ag,
        Ws_seen, bs_seen, Ws_near, bs_near,
        Wd_seen, bd_seen, Wr_seen, br_seen,
        Wd_near, bd_near, Wr_near, br_near,
        n_gt, n_ubs, n_ag);

    cudaStreamWaitEvent(0, evJoin, 0);

    k_gat<<<dim3((n_ag + 7) / 8, 2), 256>>>(attn_seen, attn_near, n_ag);

    k_gemm<<<dim3(HID / 128, (n_ag + 127) / 128), 256>>>(b_aggr, out, n_ag);
}